// round 2
// baseline (speedup 1.0000x reference)
#include <cuda_runtime.h>
#include <cuda_bf16.h>
#include <cstdint>

// ============================================================================
// Problem constants
// ============================================================================
#define NROWS 8192
#define DDIM  1024
#define INV_T 14.285714285714285714f   // 1/0.07 ; also the static logit max M
#define K2E   20.60992915f             // INV_T * log2(e)

#define TILE 128
#define KCHUNK 64
#define NCHUNKS (DDIM / KCHUNK)   // 16
#define NBLK (NROWS / TILE)       // 64
#define STAGES 3
#define STAGE_BYTES 32768         // A(16KB) + B(16KB) per stage

// ============================================================================
// Device scratch (allocation-free rule: __device__ globals)
// ============================================================================
__device__ __nv_bfloat16 g_imgn[NROWS * DDIM];
__device__ __nv_bfloat16 g_txtn[NROWS * DDIM];
__device__ float g_rowsum[NROWS];
__device__ float g_colsum[NROWS];
__device__ float g_diag;

// ============================================================================
// Helpers (sm_80-era instructions only: cp.async, ldmatrix, mma.sync bf16)
// ============================================================================
__device__ __forceinline__ uint32_t smem_to_u32(const void* smem_ptr) {
    uint32_t addr;
    asm("{ .reg .u64 tmp; cvta.to.shared.u64 tmp, %1; cvt.u32.u64 %0, tmp; }"
        : "=r"(addr) : "l"(smem_ptr));
    return addr;
}

__device__ __forceinline__ void cp_async16(uint32_t saddr, const void* gptr) {
    asm volatile("cp.async.cg.shared.global [%0], [%1], 16;"
                 :: "r"(saddr), "l"(gptr) : "memory");
}
#define CP_ASYNC_COMMIT() asm volatile("cp.async.commit_group;" ::: "memory")
#define CP_ASYNC_WAIT1()  asm volatile("cp.async.wait_group 1;"  ::: "memory")

__device__ __forceinline__ void ldmatrix_x4(uint32_t r[4], uint32_t saddr) {
    asm volatile("ldmatrix.sync.aligned.m8n8.x4.shared.b16 {%0,%1,%2,%3}, [%4];"
                 : "=r"(r[0]), "=r"(r[1]), "=r"(r[2]), "=r"(r[3]) : "r"(saddr));
}

__device__ __forceinline__ void mma_bf16(float c[4], const uint32_t a[4],
                                         uint32_t b0, uint32_t b1) {
    asm volatile(
        "mma.sync.aligned.m16n8k16.row.col.f32.bf16.bf16.f32 "
        "{%0,%1,%2,%3}, {%4,%5,%6,%7}, {%8,%9}, {%0,%1,%2,%3};"
        : "+f"(c[0]), "+f"(c[1]), "+f"(c[2]), "+f"(c[3])
        : "r"(a[0]), "r"(a[1]), "r"(a[2]), "r"(a[3]), "r"(b0), "r"(b1));
}

#define SMEM_SWIZZLE_128B(byte_offset) \
    ((byte_offset) ^ (((byte_offset) >> 3) & 0x70))

// ============================================================================
// SMEM layout (GEMM kernel): 3 pipeline stages + small epilogue region
// ============================================================================
#define SM_STAGE0   0
#define SM_EPI      (STAGES * STAGE_BYTES)       // 98304
#define SM_ROWRED   (SM_EPI)                     // 128 floats
#define SM_COLRED   (SM_EPI + 512)               // 128 floats
#define SM_DIAG     (SM_EPI + 1024)              // 1 float
#define SMEM_TOTAL  (SM_EPI + 1040)

// ============================================================================
// Kernel 1: zero the accumulators
// ============================================================================
__global__ void zero_kernel() {
    int i = blockIdx.x * blockDim.x + threadIdx.x;
    if (i < NROWS) { g_rowsum[i] = 0.0f; g_colsum[i] = 0.0f; }
    if (i == 0) g_diag = 0.0f;
}

// ============================================================================
// Kernel 2: normalize rows (eps-clamped) + pack to bf16. grid (8192,2), 128thr
// ============================================================================
__global__ void normalize_kernel(const float* __restrict__ img,
                                 const float* __restrict__ txt) {
    int row = blockIdx.x;
    const float* src = blockIdx.y ? txt : img;
    __nv_bfloat16* dst = blockIdx.y ? g_txtn : g_imgn;
    int t = threadIdx.x;

    const float4* s4 = reinterpret_cast<const float4*>(src + (size_t)row * DDIM) + t * 2;
    float4 v0 = s4[0];
    float4 v1 = s4[1];
    float ss = v0.x * v0.x + v0.y * v0.y + v0.z * v0.z + v0.w * v0.w
             + v1.x * v1.x + v1.y * v1.y + v1.z * v1.z + v1.w * v1.w;
#pragma unroll
    for (int o = 16; o; o >>= 1) ss += __shfl_xor_sync(0xffffffffu, ss, o);

    __shared__ float ws[4];
    if ((t & 31) == 0) ws[t >> 5] = ss;
    __syncthreads();
    float tot = ws[0] + ws[1] + ws[2] + ws[3];
    float scale = 1.0f / fmaxf(sqrtf(tot), 1e-8f);

    __nv_bfloat162 h0 = __floats2bfloat162_rn(v0.x * scale, v0.y * scale);
    __nv_bfloat162 h1 = __floats2bfloat162_rn(v0.z * scale, v0.w * scale);
    __nv_bfloat162 h2 = __floats2bfloat162_rn(v1.x * scale, v1.y * scale);
    __nv_bfloat162 h3 = __floats2bfloat162_rn(v1.z * scale, v1.w * scale);
    uint4 o;
    o.x = *reinterpret_cast<uint32_t*>(&h0);
    o.y = *reinterpret_cast<uint32_t*>(&h1);
    o.z = *reinterpret_cast<uint32_t*>(&h2);
    o.w = *reinterpret_cast<uint32_t*>(&h3);
    reinterpret_cast<uint4*>(dst + (size_t)row * DDIM)[t] = o;
}

// ============================================================================
// Kernel 3: fused GEMM + exp + row/col/diag reductions
//   grid (64,64), block 256 (8 warps: 2 along M x 4 along N; warp tile 64x32)
//   mma.sync m16n8k16 bf16, cp.async 3-stage pipeline, SW128 smem swizzle
// ============================================================================
__global__ void __launch_bounds__(256, 1) gemm_loss_kernel() {
    extern __shared__ char smem[];
    const uint32_t sb = smem_to_u32(smem);
    const int tid  = threadIdx.x;
    const int wid  = tid >> 5;
    const int lane = tid & 31;
    const int warp_m = wid >> 2;    // 0..1
    const int warp_n = wid & 3;     // 0..3
    const int bi = blockIdx.y;
    const int bj = blockIdx.x;

    float* rowred = reinterpret_cast<float*>(smem + SM_ROWRED);
    float* colred = reinterpret_cast<float*>(smem + SM_COLRED);
    float* dsum   = reinterpret_cast<float*>(smem + SM_DIAG);
    if (tid < 128) { rowred[tid] = 0.0f; colred[tid] = 0.0f; }
    if (tid == 0) dsum[0] = 0.0f;

    // ---- global load plan: 8 x 16B per thread per stage (A 4 + B 4) ----
    const uint4* Ag = reinterpret_cast<const uint4*>(g_imgn) + (size_t)bi * TILE * (DDIM / 8);
    const uint4* Bg = reinterpret_cast<const uint4*>(g_txtn) + (size_t)bj * TILE * (DDIM / 8);

    uint32_t sw_off[4];
    uint32_t gm_off[4];
#pragma unroll
    for (int i = 0; i < 4; i++) {
        int u = tid + 256 * i;                // 1024 16B-units per 128x64 tile
        int row = u >> 3, c16 = u & 7;
        sw_off[i] = SMEM_SWIZZLE_128B((uint32_t)(row * 128 + c16 * 16));
        gm_off[i] = (uint32_t)(row * (DDIM / 8) + c16);
    }

    // ---- prologue: stages 0 and 1 ----
#pragma unroll
    for (int s = 0; s < 2; s++) {
        uint32_t sA = sb + s * STAGE_BYTES;
        uint32_t sB = sA + 16384;
#pragma unroll
        for (int i = 0; i < 4; i++) {
            cp_async16(sA + sw_off[i], Ag + gm_off[i] + s * 8);
            cp_async16(sB + sw_off[i], Bg + gm_off[i] + s * 8);
        }
        CP_ASYNC_COMMIT();
    }

    // ---- per-thread ldmatrix address components ----
    const uint32_t aRowByte = (uint32_t)((warp_m * 64 + (lane & 15)) * 128);
    const uint32_t aXor = (uint32_t)((lane & 7) << 4);
    const uint32_t aKB  = (uint32_t)((lane >> 4) * 16);
    const uint32_t bRowByte =
        (uint32_t)((warp_n * 32 + (lane & 7) + ((lane >> 4) & 1) * 8) * 128);
    const uint32_t bXor = (uint32_t)((lane & 7) << 4);
    const uint32_t bKB  = (uint32_t)(((lane >> 3) & 1) * 16);

    float acc[4][4][4];
#pragma unroll
    for (int mt = 0; mt < 4; mt++)
#pragma unroll
        for (int nt = 0; nt < 4; nt++)
#pragma unroll
            for (int e = 0; e < 4; e++) acc[mt][nt][e] = 0.0f;

    // ---- mainloop ----
    int slot_c = 0, slot_p = 2;
#pragma unroll 1
    for (int k = 0; k < NCHUNKS; k++) {
        CP_ASYNC_WAIT1();
        __syncthreads();

        if (k + 2 < NCHUNKS) {
            uint32_t sA = sb + slot_p * STAGE_BYTES;
            uint32_t sB = sA + 16384;
#pragma unroll
            for (int i = 0; i < 4; i++) {
                cp_async16(sA + sw_off[i], Ag + gm_off[i] + (k + 2) * 8);
                cp_async16(sB + sw_off[i], Bg + gm_off[i] + (k + 2) * 8);
            }
        }
        CP_ASYNC_COMMIT();

        const uint32_t sAs = sb + slot_c * STAGE_BYTES;
        const uint32_t sBs = sAs + 16384;
#pragma unroll
        for (int ks = 0; ks < 4; ks++) {
            uint32_t a[4][4];
#pragma unroll
            for (int mt = 0; mt < 4; mt++) {
                uint32_t addr = sAs + aRowByte + (uint32_t)(mt * 16 * 128)
                              + (((uint32_t)(ks * 32) + aKB) ^ aXor);
                ldmatrix_x4(a[mt], addr);
            }
            uint32_t bf[2][4];
#pragma unroll
            for (int p = 0; p < 2; p++) {
                uint32_t addr = sBs + bRowByte + (uint32_t)(p * 16 * 128)
                              + (((uint32_t)(ks * 32) + bKB) ^ bXor);
                ldmatrix_x4(bf[p], addr);
            }
#pragma unroll
            for (int mt = 0; mt < 4; mt++)
#pragma unroll
                for (int nt = 0; nt < 4; nt++) {
                    const uint32_t b0 = bf[nt >> 1][(nt & 1) * 2 + 0];
                    const uint32_t b1 = bf[nt >> 1][(nt & 1) * 2 + 1];
                    mma_bf16(acc[mt][nt], a[mt], b0, b1);
                }
        }
        slot_c = (slot_c == 2) ? 0 : slot_c + 1;
        slot_p = (slot_p == 2) ? 0 : slot_p + 1;
    }

    // ---- epilogue: exp + reductions ----
    const int g  = lane >> 2;    // 0..7 : row within 8
    const int t4 = lane & 3;     // 0..3 : column pair selector
    float rs0[4] = {0, 0, 0, 0}, rs1[4] = {0, 0, 0, 0};
    float cs0[4] = {0, 0, 0, 0}, cs1[4] = {0, 0, 0, 0};
    float dloc = 0.0f;
    const bool diagcta = (bi == bj);

#pragma unroll
    for (int mt = 0; mt < 4; mt++) {
#pragma unroll
        for (int nt = 0; nt < 4; nt++) {
            float d0 = acc[mt][nt][0], d1 = acc[mt][nt][1];
            float d2 = acc[mt][nt][2], d3 = acc[mt][nt][3];
            float e0 = exp2f(fmaf(d0, K2E, -K2E));
            float e1 = exp2f(fmaf(d1, K2E, -K2E));
            float e2 = exp2f(fmaf(d2, K2E, -K2E));
            float e3 = exp2f(fmaf(d3, K2E, -K2E));
            rs0[mt] += e0 + e1;  rs1[mt] += e2 + e3;
            cs0[nt] += e0 + e2;  cs1[nt] += e1 + e3;
            if (diagcta) {
                int r0 = warp_m * 64 + mt * 16 + g;
                int c0 = warp_n * 32 + nt * 8 + 2 * t4;
                if (r0 == c0)         dloc += d0;
                if (r0 == c0 + 1)     dloc += d1;
                if (r0 + 8 == c0)     dloc += d2;
                if (r0 + 8 == c0 + 1) dloc += d3;
            }
        }
    }

    // row sums: reduce across the 4 lanes sharing a row (xor 1, 2)
#pragma unroll
    for (int mt = 0; mt < 4; mt++) {
        float v0 = rs0[mt], v1 = rs1[mt];
        v0 += __shfl_xor_sync(0xffffffffu, v0, 1);
        v0 += __shfl_xor_sync(0xffffffffu, v0, 2);
        v1 += __shfl_xor_sync(0xffffffffu, v1, 1);
        v1 += __shfl_xor_sync(0xffffffffu, v1, 2);
        if (t4 == 0) {
            int r = warp_m * 64 + mt * 16 + g;
            atomicAdd(&rowred[r], v0);
            atomicAdd(&rowred[r + 8], v1);
        }
    }
    // col sums: reduce across the 8 groups (xor 4, 8, 16)
#pragma unroll
    for (int nt = 0; nt < 4; nt++) {
        float u0 = cs0[nt], u1 = cs1[nt];
        u0 += __shfl_xor_sync(0xffffffffu, u0, 4);
        u0 += __shfl_xor_sync(0xffffffffu, u0, 8);
        u0 += __shfl_xor_sync(0xffffffffu, u0, 16);
        u1 += __shfl_xor_sync(0xffffffffu, u1, 4);
        u1 += __shfl_xor_sync(0xffffffffu, u1, 8);
        u1 += __shfl_xor_sync(0xffffffffu, u1, 16);
        if (lane < 4) {
            int c = warp_n * 32 + nt * 8 + 2 * t4;
            atomicAdd(&colred[c], u0);
            atomicAdd(&colred[c + 1], u1);
        }
    }
    if (diagcta && dloc != 0.0f) atomicAdd(dsum, dloc);

    __syncthreads();
    if (tid < 128) {
        atomicAdd(&g_rowsum[bi * TILE + tid], rowred[tid]);
        atomicAdd(&g_colsum[bj * TILE + tid], colred[tid]);
    }
    if (diagcta && tid == 0) atomicAdd(&g_diag, dsum[0] * INV_T);
}

// ============================================================================
// Kernel 4: finalize — loss = M + 0.5*mean(log rowsum + log colsum) - diag/N
// ============================================================================
__global__ void finalize_kernel(float* __restrict__ out) {
    __shared__ float red[256];
    float acc = 0.0f;
    for (int i = threadIdx.x; i < NROWS; i += 256) {
        acc += logf(g_rowsum[i]) + logf(g_colsum[i]);
    }
    red[threadIdx.x] = acc;
    __syncthreads();
#pragma unroll
    for (int s = 128; s; s >>= 1) {
        if (threadIdx.x < s) red[threadIdx.x] += red[threadIdx.x + s];
        __syncthreads();
    }
    if (threadIdx.x == 0) {
        out[0] = INV_T + 0.5f * red[0] / (float)NROWS - g_diag / (float)NROWS;
    }
}

// ============================================================================
// Launch
// ============================================================================
extern "C" void kernel_launch(void* const* d_in, const int* in_sizes, int n_in,
                              void* d_out, int out_size) {
    const float* img = (const float*)d_in[0];
    const float* txt = (const float*)d_in[1];
    float* out = (float*)d_out;

    cudaFuncSetAttribute(gemm_loss_kernel,
                         cudaFuncAttributeMaxDynamicSharedMemorySize, SMEM_TOTAL);

    zero_kernel<<<NROWS / 256, 256>>>();
    normalize_kernel<<<dim3(NROWS, 2), 128>>>(img, txt);
    gemm_loss_kernel<<<dim3(NBLK, NBLK), 256, SMEM_TOTAL>>>();
    finalize_kernel<<<1, 256>>>(out);
}

// round 3
// speedup vs baseline: 1.0935x; 1.0935x over previous
#include <cuda_runtime.h>
#include <cuda_bf16.h>
#include <cstdint>

// ============================================================================
// Problem constants
// ============================================================================
#define NROWS 8192
#define DDIM  1024
#define INV_T 14.285714285714285714f   // 1/0.07 ; also the static logit max M
#define K2E   20.60992915f             // INV_T * log2(e)

#define TILE_M 128
#define TILE_N 256
#define KCHUNK 64
#define NCHUNKS (DDIM / KCHUNK)   // 16
#define NBLK_M (NROWS / TILE_M)   // 64
#define NBLK_N (NROWS / TILE_N)   // 32
#define STAGES 3
#define STAGE_A_BYTES 16384       // 128 x 64 bf16
#define STAGE_B_BYTES 32768       // 256 x 64 bf16
#define STAGE_BYTES   (STAGE_A_BYTES + STAGE_B_BYTES)   // 49152

// ============================================================================
// Device scratch (allocation-free rule: __device__ globals)
// ============================================================================
__device__ __nv_bfloat16 g_imgn[NROWS * DDIM];
__device__ __nv_bfloat16 g_txtn[NROWS * DDIM];
__device__ float g_rowsum[NROWS];
__device__ float g_colsum[NROWS];
__device__ float g_diag;

// ============================================================================
// Helpers (sm_80-era instructions only: cp.async, ldmatrix, mma.sync bf16)
// ============================================================================
__device__ __forceinline__ uint32_t smem_to_u32(const void* smem_ptr) {
    uint32_t addr;
    asm("{ .reg .u64 tmp; cvta.to.shared.u64 tmp, %1; cvt.u32.u64 %0, tmp; }"
        : "=r"(addr) : "l"(smem_ptr));
    return addr;
}

__device__ __forceinline__ void cp_async16(uint32_t saddr, const void* gptr) {
    asm volatile("cp.async.cg.shared.global [%0], [%1], 16;"
                 :: "r"(saddr), "l"(gptr) : "memory");
}
#define CP_ASYNC_COMMIT() asm volatile("cp.async.commit_group;" ::: "memory")
#define CP_ASYNC_WAIT1()  asm volatile("cp.async.wait_group 1;"  ::: "memory")

__device__ __forceinline__ void ldmatrix_x4(uint32_t r[4], uint32_t saddr) {
    asm volatile("ldmatrix.sync.aligned.m8n8.x4.shared.b16 {%0,%1,%2,%3}, [%4];"
                 : "=r"(r[0]), "=r"(r[1]), "=r"(r[2]), "=r"(r[3]) : "r"(saddr));
}

__device__ __forceinline__ void mma_bf16(float c[4], const uint32_t a[4],
                                         uint32_t b0, uint32_t b1) {
    asm volatile(
        "mma.sync.aligned.m16n8k16.row.col.f32.bf16.bf16.f32 "
        "{%0,%1,%2,%3}, {%4,%5,%6,%7}, {%8,%9}, {%0,%1,%2,%3};"
        : "+f"(c[0]), "+f"(c[1]), "+f"(c[2]), "+f"(c[3])
        : "r"(a[0]), "r"(a[1]), "r"(a[2]), "r"(a[3]), "r"(b0), "r"(b1));
}

#define SMEM_SWIZZLE_128B(byte_offset) \
    ((byte_offset) ^ (((byte_offset) >> 3) & 0x70))

// ============================================================================
// SMEM layout (GEMM kernel): 3 pipeline stages + small epilogue region
// ============================================================================
#define SM_EPI      (STAGES * STAGE_BYTES)       // 147456
#define SM_ROWRED   (SM_EPI)                     // 128 floats
#define SM_COLRED   (SM_EPI + 512)               // 256 floats
#define SM_DIAG     (SM_EPI + 1536)              // 1 float
#define SMEM_TOTAL  (SM_EPI + 1552)

// ============================================================================
// Kernel 1: zero the accumulators
// ============================================================================
__global__ void zero_kernel() {
    int i = blockIdx.x * blockDim.x + threadIdx.x;
    if (i < NROWS) { g_rowsum[i] = 0.0f; g_colsum[i] = 0.0f; }
    if (i == 0) g_diag = 0.0f;
}

// ============================================================================
// Kernel 2: normalize rows (eps-clamped) + pack to bf16. grid (8192,2), 128thr
// ============================================================================
__global__ void normalize_kernel(const float* __restrict__ img,
                                 const float* __restrict__ txt) {
    int row = blockIdx.x;
    const float* src = blockIdx.y ? txt : img;
    __nv_bfloat16* dst = blockIdx.y ? g_txtn : g_imgn;
    int t = threadIdx.x;

    const float4* s4 = reinterpret_cast<const float4*>(src + (size_t)row * DDIM) + t * 2;
    float4 v0 = s4[0];
    float4 v1 = s4[1];
    float ss = v0.x * v0.x + v0.y * v0.y + v0.z * v0.z + v0.w * v0.w
             + v1.x * v1.x + v1.y * v1.y + v1.z * v1.z + v1.w * v1.w;
#pragma unroll
    for (int o = 16; o; o >>= 1) ss += __shfl_xor_sync(0xffffffffu, ss, o);

    __shared__ float ws[4];
    if ((t & 31) == 0) ws[t >> 5] = ss;
    __syncthreads();
    float tot = ws[0] + ws[1] + ws[2] + ws[3];
    float scale = 1.0f / fmaxf(sqrtf(tot), 1e-8f);

    __nv_bfloat162 h0 = __floats2bfloat162_rn(v0.x * scale, v0.y * scale);
    __nv_bfloat162 h1 = __floats2bfloat162_rn(v0.z * scale, v0.w * scale);
    __nv_bfloat162 h2 = __floats2bfloat162_rn(v1.x * scale, v1.y * scale);
    __nv_bfloat162 h3 = __floats2bfloat162_rn(v1.z * scale, v1.w * scale);
    uint4 o;
    o.x = *reinterpret_cast<uint32_t*>(&h0);
    o.y = *reinterpret_cast<uint32_t*>(&h1);
    o.z = *reinterpret_cast<uint32_t*>(&h2);
    o.w = *reinterpret_cast<uint32_t*>(&h3);
    reinterpret_cast<uint4*>(dst + (size_t)row * DDIM)[t] = o;
}

// ============================================================================
// Kernel 3: fused GEMM + exp + row/col/diag reductions
//   grid (32,64), block 256 (8 warps: 2(M) x 4(N); warp tile 64x64)
//   CTA tile 128x256, mma.sync m16n8k16 bf16, 3-stage cp.async, SW128 swizzle
// ============================================================================
__global__ void __launch_bounds__(256, 1) gemm_loss_kernel() {
    extern __shared__ char smem[];
    const uint32_t sb = smem_to_u32(smem);
    const int tid  = threadIdx.x;
    const int wid  = tid >> 5;
    const int lane = tid & 31;
    const int warp_m = wid >> 2;    // 0..1
    const int warp_n = wid & 3;     // 0..3
    const int bi = blockIdx.y;      // M tile (128)
    const int bj = blockIdx.x;      // N tile (256)

    float* rowred = reinterpret_cast<float*>(smem + SM_ROWRED);
    float* colred = reinterpret_cast<float*>(smem + SM_COLRED);
    float* dsum   = reinterpret_cast<float*>(smem + SM_DIAG);
    if (tid < 128) rowred[tid] = 0.0f;
    colred[tid] = 0.0f;
    if (tid == 0) dsum[0] = 0.0f;

    // ---- global load plan per stage: A 4 x 16B, B 8 x 16B per thread ----
    const uint4* Ag = reinterpret_cast<const uint4*>(g_imgn) + (size_t)bi * TILE_M * (DDIM / 8);
    const uint4* Bg = reinterpret_cast<const uint4*>(g_txtn) + (size_t)bj * TILE_N * (DDIM / 8);

    uint32_t sw_off[8];
    uint32_t gm_off[8];
#pragma unroll
    for (int i = 0; i < 8; i++) {
        int u = tid + 256 * i;                // 16B-unit index within tile
        int row = u >> 3, c16 = u & 7;
        sw_off[i] = SMEM_SWIZZLE_128B((uint32_t)(row * 128 + c16 * 16));
        gm_off[i] = (uint32_t)(row * (DDIM / 8) + c16);
    }

    // ---- prologue: stages 0 and 1 ----
#pragma unroll
    for (int s = 0; s < 2; s++) {
        uint32_t sA = sb + s * STAGE_BYTES;
        uint32_t sB = sA + STAGE_A_BYTES;
#pragma unroll
        for (int i = 0; i < 4; i++)
            cp_async16(sA + sw_off[i], Ag + gm_off[i] + s * 8);
#pragma unroll
        for (int i = 0; i < 8; i++)
            cp_async16(sB + sw_off[i], Bg + gm_off[i] + s * 8);
        CP_ASYNC_COMMIT();
    }

    // ---- per-thread ldmatrix address components ----
    const uint32_t aRowByte = (uint32_t)((warp_m * 64 + (lane & 15)) * 128);
    const uint32_t aXor = (uint32_t)((lane & 7) << 4);
    const uint32_t aKB  = (uint32_t)((lane >> 4) * 16);
    const uint32_t bRowByte =
        (uint32_t)((warp_n * 64 + (lane & 7) + ((lane >> 4) & 1) * 8) * 128);
    const uint32_t bXor = (uint32_t)((lane & 7) << 4);
    const uint32_t bKB  = (uint32_t)(((lane >> 3) & 1) * 16);

    float acc[4][8][4];
#pragma unroll
    for (int mt = 0; mt < 4; mt++)
#pragma unroll
        for (int nt = 0; nt < 8; nt++)
#pragma unroll
            for (int e = 0; e < 4; e++) acc[mt][nt][e] = 0.0f;

    // ---- mainloop ----
    int slot_c = 0, slot_p = 2;
#pragma unroll 1
    for (int k = 0; k < NCHUNKS; k++) {
        CP_ASYNC_WAIT1();
        __syncthreads();

        if (k + 2 < NCHUNKS) {
            uint32_t sA = sb + slot_p * STAGE_BYTES;
            uint32_t sB = sA + STAGE_A_BYTES;
#pragma unroll
            for (int i = 0; i < 4; i++)
                cp_async16(sA + sw_off[i], Ag + gm_off[i] + (k + 2) * 8);
#pragma unroll
            for (int i = 0; i < 8; i++)
                cp_async16(sB + sw_off[i], Bg + gm_off[i] + (k + 2) * 8);
        }
        CP_ASYNC_COMMIT();

        const uint32_t sAs = sb + slot_c * STAGE_BYTES;
        const uint32_t sBs = sAs + STAGE_A_BYTES;
#pragma unroll
        for (int ks = 0; ks < 4; ks++) {
            uint32_t a[4][4];
#pragma unroll
            for (int mt = 0; mt < 4; mt++) {
                uint32_t addr = sAs + aRowByte + (uint32_t)(mt * 16 * 128)
                              + (((uint32_t)(ks * 32) + aKB) ^ aXor);
                ldmatrix_x4(a[mt], addr);
            }
            uint32_t bf[4][4];    // p covers 16 n-cols each -> 64 per warp
#pragma unroll
            for (int p = 0; p < 4; p++) {
                uint32_t addr = sBs + bRowByte + (uint32_t)(p * 16 * 128)
                              + (((uint32_t)(ks * 32) + bKB) ^ bXor);
                ldmatrix_x4(bf[p], addr);
            }
#pragma unroll
            for (int mt = 0; mt < 4; mt++)
#pragma unroll
                for (int nt = 0; nt < 8; nt++) {
                    const uint32_t b0 = bf[nt >> 1][(nt & 1) * 2 + 0];
                    const uint32_t b1 = bf[nt >> 1][(nt & 1) * 2 + 1];
                    mma_bf16(acc[mt][nt], a[mt], b0, b1);
                }
        }
        slot_c = (slot_c == 2) ? 0 : slot_c + 1;
        slot_p = (slot_p == 2) ? 0 : slot_p + 1;
    }

    // ---- epilogue: exp + reductions ----
    const int g  = lane >> 2;    // 0..7 : row within 8
    const int t4 = lane & 3;     // 0..3 : column pair selector
    // diag: global row bi*128+r  ==  global col bj*256+c  ->  c = r + doff
    const int doff = bi * TILE_M - bj * TILE_N;
    const bool diagcta = (doff == 0) || (doff == TILE_M);
    float rs0[4] = {0, 0, 0, 0}, rs1[4] = {0, 0, 0, 0};
    float cs0[8] = {0, 0, 0, 0, 0, 0, 0, 0}, cs1[8] = {0, 0, 0, 0, 0, 0, 0, 0};
    float dloc = 0.0f;

#pragma unroll
    for (int mt = 0; mt < 4; mt++) {
#pragma unroll
        for (int nt = 0; nt < 8; nt++) {
            float d0 = acc[mt][nt][0], d1 = acc[mt][nt][1];
            float d2 = acc[mt][nt][2], d3 = acc[mt][nt][3];
            float e0 = exp2f(fmaf(d0, K2E, -K2E));
            float e1 = exp2f(fmaf(d1, K2E, -K2E));
            float e2 = exp2f(fmaf(d2, K2E, -K2E));
            float e3 = exp2f(fmaf(d3, K2E, -K2E));
            rs0[mt] += e0 + e1;  rs1[mt] += e2 + e3;
            cs0[nt] += e0 + e2;  cs1[nt] += e1 + e3;
            if (diagcta) {
                int r0 = warp_m * 64 + mt * 16 + g;
                int c0 = warp_n * 64 + nt * 8 + 2 * t4;
                if (c0 == r0 + doff)         dloc += d0;
                if (c0 + 1 == r0 + doff)     dloc += d1;
                if (c0 == r0 + 8 + doff)     dloc += d2;
                if (c0 + 1 == r0 + 8 + doff) dloc += d3;
            }
        }
    }

    // row sums: reduce across the 4 lanes sharing a row (xor 1, 2)
#pragma unroll
    for (int mt = 0; mt < 4; mt++) {
        float v0 = rs0[mt], v1 = rs1[mt];
        v0 += __shfl_xor_sync(0xffffffffu, v0, 1);
        v0 += __shfl_xor_sync(0xffffffffu, v0, 2);
        v1 += __shfl_xor_sync(0xffffffffu, v1, 1);
        v1 += __shfl_xor_sync(0xffffffffu, v1, 2);
        if (t4 == 0) {
            int r = warp_m * 64 + mt * 16 + g;
            atomicAdd(&rowred[r], v0);
            atomicAdd(&rowred[r + 8], v1);
        }
    }
    // col sums: reduce across the 8 groups (xor 4, 8, 16)
#pragma unroll
    for (int nt = 0; nt < 8; nt++) {
        float u0 = cs0[nt], u1 = cs1[nt];
        u0 += __shfl_xor_sync(0xffffffffu, u0, 4);
        u0 += __shfl_xor_sync(0xffffffffu, u0, 8);
        u0 += __shfl_xor_sync(0xffffffffu, u0, 16);
        u1 += __shfl_xor_sync(0xffffffffu, u1, 4);
        u1 += __shfl_xor_sync(0xffffffffu, u1, 8);
        u1 += __shfl_xor_sync(0xffffffffu, u1, 16);
        if (lane < 4) {
            int c = warp_n * 64 + nt * 8 + 2 * t4;
            atomicAdd(&colred[c], u0);
            atomicAdd(&colred[c + 1], u1);
        }
    }
    if (diagcta && dloc != 0.0f) atomicAdd(dsum, dloc);

    __syncthreads();
    if (tid < 128) atomicAdd(&g_rowsum[bi * TILE_M + tid], rowred[tid]);
    atomicAdd(&g_colsum[bj * TILE_N + tid], colred[tid]);
    if (diagcta && tid == 0) atomicAdd(&g_diag, dsum[0] * INV_T);
}

// ============================================================================
// Kernel 4: finalize — loss = M + 0.5*mean(log rowsum + log colsum) - diag/N
// ============================================================================
__global__ void finalize_kernel(float* __restrict__ out) {
    __shared__ float red[32];
    float acc = 0.0f;
    for (int i = threadIdx.x; i < NROWS; i += 1024) {
        acc += logf(g_rowsum[i]) + logf(g_colsum[i]);
    }
#pragma unroll
    for (int o = 16; o; o >>= 1) acc += __shfl_xor_sync(0xffffffffu, acc, o);
    if ((threadIdx.x & 31) == 0) red[threadIdx.x >> 5] = acc;
    __syncthreads();
    if (threadIdx.x < 32) {
        float v = red[threadIdx.x];
#pragma unroll
        for (int o = 16; o; o >>= 1) v += __shfl_xor_sync(0xffffffffu, v, o);
        if (threadIdx.x == 0)
            out[0] = INV_T + 0.5f * v / (float)NROWS - g_diag / (float)NROWS;
    }
}

// ============================================================================
// Launch
// ============================================================================
extern "C" void kernel_launch(void* const* d_in, const int* in_sizes, int n_in,
                              void* d_out, int out_size) {
    const float* img = (const float*)d_in[0];
    const float* txt = (const float*)d_in[1];
    float* out = (float*)d_out;

    cudaFuncSetAttribute(gemm_loss_kernel,
                         cudaFuncAttributeMaxDynamicSharedMemorySize, SMEM_TOTAL);

    zero_kernel<<<NROWS / 256, 256>>>();
    normalize_kernel<<<dim3(NROWS, 2), 128>>>(img, txt);
    gemm_loss_kernel<<<dim3(NBLK_N, NBLK_M), 256, SMEM_TOTAL>>>();
    finalize_kernel<<<1, 1024>>>(out);
}